// round 1
// baseline (speedup 1.0000x reference)
#include <cuda_runtime.h>

// SPHeroConv: out[o,f] = sum_{e in o} sum_s sph[e,s] * (feat[nidx[e]] @ K[s])[f] + bias[f]
// Reassociated: g[o,s,c] = sum_e sph[e,s]*feat[e,c]  (stage 1, per-CTA in smem, transposed)
//               out[o,:] = g[o,:,:] flattened (256) @ Kflat (256x64) + bias  (stage 2)
//
// Fixed problem shape: N_OUT=50000, DEG=16 (uniform row_splits), C=64, F=64.

#define BM        64      // output points per CTA
#define CDIM      64
#define FDIM      64
#define KDIM      256     // 4 * CDIM
#define AS_STRIDE 68      // BM + 4 pad (keeps float4 alignment: 68*4 % 16 == 0)

__global__ __launch_bounds__(256, 1)
void spconv_fused_kernel(const float* __restrict__ feat,      // [N_IN, 64]
                         const float* __restrict__ ipos,      // [N_IN, 3]
                         const float* __restrict__ opos,      // [N_OUT, 3]
                         const float* __restrict__ extents,   // [1]
                         const float* __restrict__ kern,      // [4,64,64] == [256,64]
                         const float* __restrict__ bias,      // [64]
                         const int*   __restrict__ nidx,      // [E]
                         float*       __restrict__ out,       // [N_OUT, 64]
                         int nOut, int deg)
{
    extern __shared__ float smem[];
    float* As = smem;                      // [KDIM][AS_STRIDE]  (g transposed, k-major)
    float* Bs = smem + KDIM * AS_STRIDE;   // [KDIM][FDIM]

    const int tid = threadIdx.x;

    // ---- load kernel matrix into Bs (16384 floats, coalesced float4 copy) ----
    {
        const float4* src = reinterpret_cast<const float4*>(kern);
        float4*       dst = reinterpret_cast<float4*>(Bs);
        #pragma unroll
        for (int i = 0; i < 16; i++)
            dst[i * 256 + tid] = src[i * 256 + tid];
    }

    // ---- stage 1: gather + weighted accumulate g[s][c] for this CTA's 64 points ----
    // 4 threads per point; thread q handles c in [16q, 16q+16)
    const int ptl = tid >> 2;          // local point 0..63
    const int q   = tid & 3;           // c-quarter
    const int pt  = blockIdx.x * BM + ptl;

    float g[4][16];
    #pragma unroll
    for (int s = 0; s < 4; s++)
        #pragma unroll
        for (int c = 0; c < 16; c++) g[s][c] = 0.0f;

    if (pt < nOut) {
        const float ox = opos[pt * 3 + 0];
        const float oy = opos[pt * 3 + 1];
        const float oz = opos[pt * 3 + 2];
        const float inv_ext = __fdividef(1.0f, extents[0]);
        const long  ebase = (long)pt * deg;

        for (int k = 0; k < deg; k++) {
            const int n = nidx[ebase + k];
            const float dx = ipos[n * 3 + 0] - ox;
            const float dy = ipos[n * 3 + 1] - oy;
            const float dz = ipos[n * 3 + 2] - oz;

            const float r2p  = dx * dx + dy * dy;
            const float r2   = r2p + dz * dz;
            // max(sqrt(x),1e-10) == sqrt(max(x,1e-20)); x/max(sqrt,eps) == x*rsqrt(max)
            const float rinv  = rsqrtf(fmaxf(r2,  1e-20f));
            const float rpinv = rsqrtf(fmaxf(r2p, 1e-20f));
            float sph[4];
            sph[0] = (r2 * rinv) * inv_ext;   // r_normalized
            sph[1] = dz * rinv;               // cos_phi
            sph[2] = dy * rpinv;              // sin_theta
            sph[3] = dx * rpinv;              // cos_theta

            const float4* fb = reinterpret_cast<const float4*>(feat + (long)n * CDIM) + q * 4;
            #pragma unroll
            for (int j = 0; j < 4; j++) {
                const float4 v = fb[j];
                const float vv[4] = { v.x, v.y, v.z, v.w };
                #pragma unroll
                for (int s = 0; s < 4; s++)
                    #pragma unroll
                    for (int cc = 0; cc < 4; cc++)
                        g[s][j * 4 + cc] += sph[s] * vv[cc];
            }
        }
    }

    // write g transposed into As: row r = s*64 + q*16 + cc, col = ptl
    #pragma unroll
    for (int s = 0; s < 4; s++)
        #pragma unroll
        for (int cc = 0; cc < 16; cc++)
            As[(s * CDIM + q * 16 + cc) * AS_STRIDE + ptl] = g[s][cc];

    __syncthreads();

    // ---- stage 2: [64 x 256] @ [256 x 64] GEMM, 4x4 micro-tile per thread ----
    const int ty = tid >> 4;           // 0..15
    const int tx = tid & 15;           // 0..15
    const int ry = ty * 4;             // local point rows
    const int cx = tx * 4;             // feature cols

    float acc[4][4];
    {
        const float4 bb = *reinterpret_cast<const float4*>(bias + cx);
        #pragma unroll
        for (int i = 0; i < 4; i++) {
            acc[i][0] = bb.x; acc[i][1] = bb.y; acc[i][2] = bb.z; acc[i][3] = bb.w;
        }
    }

    #pragma unroll 8
    for (int k = 0; k < KDIM; k++) {
        const float4 a = *reinterpret_cast<const float4*>(As + k * AS_STRIDE + ry);
        const float4 b = *reinterpret_cast<const float4*>(Bs + k * FDIM + cx);
        const float aa[4] = { a.x, a.y, a.z, a.w };
        const float bbv[4] = { b.x, b.y, b.z, b.w };
        #pragma unroll
        for (int i = 0; i < 4; i++)
            #pragma unroll
            for (int j = 0; j < 4; j++)
                acc[i][j] += aa[i] * bbv[j];
    }

    const int ptBase = blockIdx.x * BM;
    #pragma unroll
    for (int i = 0; i < 4; i++) {
        const int p = ptBase + ry + i;
        if (p < nOut) {
            float4 r;
            r.x = acc[i][0]; r.y = acc[i][1]; r.z = acc[i][2]; r.w = acc[i][3];
            *reinterpret_cast<float4*>(out + (long)p * FDIM + cx) = r;
        }
    }
}

extern "C" void kernel_launch(void* const* d_in, const int* in_sizes, int n_in,
                              void* d_out, int out_size)
{
    const float* feat    = (const float*)d_in[0];
    const float* ipos    = (const float*)d_in[1];
    const float* opos    = (const float*)d_in[2];
    const float* extents = (const float*)d_in[3];
    const float* kern    = (const float*)d_in[4];
    const float* bias    = (const float*)d_in[5];
    const int*   nidx    = (const int*)d_in[6];
    // d_in[7] = neighbors_row_splits (uniform DEG*arange; deg derived below)

    float* out = (float*)d_out;

    const int nOut = in_sizes[2] / 3;
    const int deg  = in_sizes[6] / nOut;

    const int smemBytes = (KDIM * AS_STRIDE + KDIM * FDIM) * (int)sizeof(float); // 135168
    cudaFuncSetAttribute(spconv_fused_kernel,
                         cudaFuncAttributeMaxDynamicSharedMemorySize, smemBytes);

    const int grid = (nOut + BM - 1) / BM;
    spconv_fused_kernel<<<grid, 256, smemBytes>>>(feat, ipos, opos, extents,
                                                  kern, bias, nidx, out, nOut, deg);
}

// round 2
// speedup vs baseline: 1.1614x; 1.1614x over previous
#include <cuda_runtime.h>

// SPHeroConv fused, R2:
//  stage 1: gather + weighted accumulate g[k][pt] into smem As (k-major, transposed)
//  stage 2: [64 x 256] @ [256 x 64] GEMM, 8x8 micro-tile, 4-way k-split,
//           B operand read directly from global (L1-resident, 64KB),
//           partials reduced through smem (reusing As region).
// smem = 69.6KB only -> 2 CTAs/SM (occupancy 2x vs R1).

#define BM        64
#define CDIM      64
#define FDIM      64
#define KDIM      256
#define AS_STRIDE 68      // 64 + 4 pad, float4-aligned rows

__global__ __launch_bounds__(256, 2)
void spconv_fused_kernel(const float* __restrict__ feat,      // [N_IN, 64]
                         const float* __restrict__ ipos,      // [N_IN, 3]
                         const float* __restrict__ opos,      // [N_OUT, 3]
                         const float* __restrict__ extents,   // [1]
                         const float* __restrict__ kern,      // [256, 64]
                         const float* __restrict__ bias,      // [64]
                         const int*   __restrict__ nidx,      // [E]
                         float*       __restrict__ out,       // [N_OUT, 64]
                         int nOut, int deg)
{
    extern __shared__ float smem[];
    float* As = smem;                      // [KDIM][AS_STRIDE] = 69632 B

    const int tid = threadIdx.x;

    // ---------------- stage 1: gather + per-point weighted feature sums ------
    // 4 threads per point; thread q handles c in [16q, 16q+16)
    const int ptl = tid >> 2;
    const int q   = tid & 3;
    const int pt  = blockIdx.x * BM + ptl;

    float g[4][16];
    #pragma unroll
    for (int s = 0; s < 4; s++)
        #pragma unroll
        for (int c = 0; c < 16; c++) g[s][c] = 0.0f;

    if (pt < nOut) {
        const float ox = opos[pt * 3 + 0];
        const float oy = opos[pt * 3 + 1];
        const float oz = opos[pt * 3 + 2];
        const float inv_ext = __fdividef(1.0f, extents[0]);
        const long  ebase = (long)pt * deg;

        #pragma unroll 4
        for (int k = 0; k < deg; k++) {
            const int n = nidx[ebase + k];
            const float dx = ipos[n * 3 + 0] - ox;
            const float dy = ipos[n * 3 + 1] - oy;
            const float dz = ipos[n * 3 + 2] - oz;

            const float r2p = dx * dx + dy * dy;
            const float r2  = r2p + dz * dz;
            const float rinv  = rsqrtf(fmaxf(r2,  1e-20f));
            const float rpinv = rsqrtf(fmaxf(r2p, 1e-20f));
            float sph[4];
            sph[0] = (r2 * rinv) * inv_ext;
            sph[1] = dz * rinv;
            sph[2] = dy * rpinv;
            sph[3] = dx * rpinv;

            const float4* fb = reinterpret_cast<const float4*>(feat + (long)n * CDIM) + q * 4;
            #pragma unroll
            for (int j = 0; j < 4; j++) {
                const float4 v = fb[j];
                const float vv[4] = { v.x, v.y, v.z, v.w };
                #pragma unroll
                for (int s = 0; s < 4; s++)
                    #pragma unroll
                    for (int cc = 0; cc < 4; cc++)
                        g[s][j * 4 + cc] += sph[s] * vv[cc];
            }
        }
    }

    // As row r = s*64 + q*16 + cc  (matches kern row index), col = ptl
    #pragma unroll
    for (int s = 0; s < 4; s++)
        #pragma unroll
        for (int cc = 0; cc < 16; cc++)
            As[(s * CDIM + q * 16 + cc) * AS_STRIDE + ptl] = g[s][cc];

    __syncthreads();

    // ---------------- stage 2: GEMM, 8x8 tile, 4-way k-split -----------------
    const int grp = tid >> 6;            // k-split group 0..3
    const int gt  = tid & 63;
    const int tr  = (gt >> 3) << 3;      // row base (point)
    const int tc  = (gt & 7) << 3;       // col base (feature)
    const int k0  = grp << 6;            // this group's k range [k0, k0+64)

    float acc[8][8];
    #pragma unroll
    for (int i = 0; i < 8; i++)
        #pragma unroll
        for (int j = 0; j < 8; j++) acc[i][j] = 0.0f;

    #pragma unroll 2
    for (int kk = 0; kk < 64; kk++) {
        const int k = k0 + kk;
        const float4 a0 = *reinterpret_cast<const float4*>(As + k * AS_STRIDE + tr);
        const float4 a1 = *reinterpret_cast<const float4*>(As + k * AS_STRIDE + tr + 4);
        const float4 b0 = *reinterpret_cast<const float4*>(kern + k * FDIM + tc);
        const float4 b1 = *reinterpret_cast<const float4*>(kern + k * FDIM + tc + 4);
        const float av[8] = { a0.x, a0.y, a0.z, a0.w, a1.x, a1.y, a1.z, a1.w };
        const float bv[8] = { b0.x, b0.y, b0.z, b0.w, b1.x, b1.y, b1.z, b1.w };
        #pragma unroll
        for (int i = 0; i < 8; i++)
            #pragma unroll
            for (int j = 0; j < 8; j++)
                acc[i][j] += av[i] * bv[j];
    }

    __syncthreads();   // all As reads complete; safe to reuse smem for partials

    // each group writes its 64x64 partial tile: buf[grp][row][col]
    {
        float* buf = smem + grp * (BM * FDIM);
        #pragma unroll
        for (int i = 0; i < 8; i++)
            #pragma unroll
            for (int j = 0; j < 8; j += 4) {
                float4 v;
                v.x = acc[i][j + 0]; v.y = acc[i][j + 1];
                v.z = acc[i][j + 2]; v.w = acc[i][j + 3];
                *reinterpret_cast<float4*>(buf + (tr + i) * FDIM + tc + j) = v;
            }
    }

    __syncthreads();

    // final reduce + bias + store: thread -> row r, 16 cols starting at cb
    const int r  = tid >> 2;
    const int cb = (tid & 3) << 4;
    const int p  = blockIdx.x * BM + r;
    if (p < nOut) {
        #pragma unroll
        for (int j4 = 0; j4 < 16; j4 += 4) {
            float4 s0 = *reinterpret_cast<const float4*>(smem + 0 * (BM*FDIM) + r * FDIM + cb + j4);
            float4 s1 = *reinterpret_cast<const float4*>(smem + 1 * (BM*FDIM) + r * FDIM + cb + j4);
            float4 s2 = *reinterpret_cast<const float4*>(smem + 2 * (BM*FDIM) + r * FDIM + cb + j4);
            float4 s3 = *reinterpret_cast<const float4*>(smem + 3 * (BM*FDIM) + r * FDIM + cb + j4);
            float4 bb = *reinterpret_cast<const float4*>(bias + cb + j4);
            float4 v;
            v.x = s0.x + s1.x + s2.x + s3.x + bb.x;
            v.y = s0.y + s1.y + s2.y + s3.y + bb.y;
            v.z = s0.z + s1.z + s2.z + s3.z + bb.z;
            v.w = s0.w + s1.w + s2.w + s3.w + bb.w;
            *reinterpret_cast<float4*>(out + (long)p * FDIM + cb + j4) = v;
        }
    }
}

extern "C" void kernel_launch(void* const* d_in, const int* in_sizes, int n_in,
                              void* d_out, int out_size)
{
    const float* feat    = (const float*)d_in[0];
    const float* ipos    = (const float*)d_in[1];
    const float* opos    = (const float*)d_in[2];
    const float* extents = (const float*)d_in[3];
    const float* kern    = (const float*)d_in[4];
    const float* bias    = (const float*)d_in[5];
    const int*   nidx    = (const int*)d_in[6];

    float* out = (float*)d_out;

    const int nOut = in_sizes[2] / 3;
    const int deg  = in_sizes[6] / nOut;

    const int smemBytes = KDIM * AS_STRIDE * (int)sizeof(float); // 69632
    cudaFuncSetAttribute(spconv_fused_kernel,
                         cudaFuncAttributeMaxDynamicSharedMemorySize, smemBytes);

    const int grid = (nOut + BM - 1) / BM;
    spconv_fused_kernel<<<grid, 256, smemBytes>>>(feat, ipos, opos, extents,
                                                  kern, bias, nidx, out, nOut, deg);
}

// round 3
// speedup vs baseline: 1.1699x; 1.0073x over previous
#include <cuda_runtime.h>

// SPHeroConv fused, R3: packed f32x2 FFMA2 in both stages (ptxas never emits
// FFMA2 from C++; explicit PTX fma.rn.f32x2 halves fma-pipe instruction count).

#define BM        64
#define CDIM      64
#define FDIM      64
#define KDIM      256
#define AS_STRIDE 68      // 64 + 4 pad; 68*4=272 bytes/row keeps 16B alignment

typedef unsigned long long u64;

__device__ __forceinline__ u64 dup2f(float x) {
    u64 r; asm("mov.b64 %0, {%1, %1};" : "=l"(r) : "f"(x)); return r;
}
__device__ __forceinline__ void ffma2(u64& d, u64 a, u64 b) {
    asm("fma.rn.f32x2 %0, %1, %2, %0;" : "+l"(d) : "l"(a), "l"(b));
}
__device__ __forceinline__ float2 unpk2(u64 v) {
    float lo, hi; asm("mov.b64 {%0, %1}, %2;" : "=f"(lo), "=f"(hi) : "l"(v));
    return make_float2(lo, hi);
}

__global__ __launch_bounds__(256, 2)
void spconv_fused_kernel(const float* __restrict__ feat,      // [N_IN, 64]
                         const float* __restrict__ ipos,      // [N_IN, 3]
                         const float* __restrict__ opos,      // [N_OUT, 3]
                         const float* __restrict__ extents,   // [1]
                         const float* __restrict__ kern,      // [256, 64]
                         const float* __restrict__ bias,      // [64]
                         const int*   __restrict__ nidx,      // [E]
                         float*       __restrict__ out,       // [N_OUT, 64]
                         int nOut, int deg)
{
    extern __shared__ float smem[];
    float* As = smem;                      // [KDIM][AS_STRIDE] = 69632 B

    const int tid = threadIdx.x;

    // ---------------- stage 1: gather + weighted feature sums (packed) ------
    const int ptl = tid >> 2;
    const int q   = tid & 3;
    const int pt  = blockIdx.x * BM + ptl;

    u64 g2[4][8];   // [s][c-pair]: pair jj covers c = (2jj, 2jj+1) of this q's 16
    #pragma unroll
    for (int s = 0; s < 4; s++)
        #pragma unroll
        for (int jj = 0; jj < 8; jj++) g2[s][jj] = 0ull;

    if (pt < nOut) {
        const float ox = opos[pt * 3 + 0];
        const float oy = opos[pt * 3 + 1];
        const float oz = opos[pt * 3 + 2];
        const float inv_ext = __fdividef(1.0f, extents[0]);
        const long  ebase = (long)pt * deg;

        #pragma unroll 4
        for (int k = 0; k < deg; k++) {
            const int n = nidx[ebase + k];
            const float dx = ipos[n * 3 + 0] - ox;
            const float dy = ipos[n * 3 + 1] - oy;
            const float dz = ipos[n * 3 + 2] - oz;

            const float r2p = dx * dx + dy * dy;
            const float r2  = r2p + dz * dz;
            const float rinv  = rsqrtf(fmaxf(r2,  1e-20f));
            const float rpinv = rsqrtf(fmaxf(r2p, 1e-20f));

            u64 sph2[4];
            sph2[0] = dup2f((r2 * rinv) * inv_ext);
            sph2[1] = dup2f(dz * rinv);
            sph2[2] = dup2f(dy * rpinv);
            sph2[3] = dup2f(dx * rpinv);

            // feat row, this q's 16 floats, as 4x 16B loads = 8 natural f32 pairs
            const ulonglong2* fb2 =
                reinterpret_cast<const ulonglong2*>(feat + (long)n * CDIM + q * 16);
            #pragma unroll
            for (int j = 0; j < 4; j++) {
                const ulonglong2 w = fb2[j];
                #pragma unroll
                for (int s = 0; s < 4; s++) {
                    ffma2(g2[s][2 * j + 0], sph2[s], w.x);
                    ffma2(g2[s][2 * j + 1], sph2[s], w.y);
                }
            }
        }
    }

    // write g transposed into As: row = s*64 + q*16 + c, col = ptl
    #pragma unroll
    for (int s = 0; s < 4; s++)
        #pragma unroll
        for (int jj = 0; jj < 8; jj++) {
            const float2 f = unpk2(g2[s][jj]);
            const int row = s * CDIM + q * 16 + 2 * jj;
            As[(row + 0) * AS_STRIDE + ptl] = f.x;
            As[(row + 1) * AS_STRIDE + ptl] = f.y;
        }

    __syncthreads();

    // ---------------- stage 2: GEMM, 8x8 tile, 4-way k-split, packed --------
    const int grp = tid >> 6;            // k-split group 0..3
    const int gt  = tid & 63;
    const int tr  = (gt >> 3) << 3;      // row base (point)
    const int tc  = (gt & 7) << 3;       // col base (feature)
    const int k0  = grp << 6;

    u64 acc2[8][4];                      // [row][col-pair]
    #pragma unroll
    for (int i = 0; i < 8; i++)
        #pragma unroll
        for (int j = 0; j < 4; j++) acc2[i][j] = 0ull;

    #pragma unroll 2
    for (int kk = 0; kk < 64; kk++) {
        const int k = k0 + kk;
        const float4 a0 = *reinterpret_cast<const float4*>(As + k * AS_STRIDE + tr);
        const float4 a1 = *reinterpret_cast<const float4*>(As + k * AS_STRIDE + tr + 4);
        u64 ad[8];
        ad[0] = dup2f(a0.x); ad[1] = dup2f(a0.y); ad[2] = dup2f(a0.z); ad[3] = dup2f(a0.w);
        ad[4] = dup2f(a1.x); ad[5] = dup2f(a1.y); ad[6] = dup2f(a1.z); ad[7] = dup2f(a1.w);

        const ulonglong2* kb = reinterpret_cast<const ulonglong2*>(kern + k * FDIM + tc);
        const ulonglong2 w0 = kb[0];
        const ulonglong2 w1 = kb[1];
        const u64 bp[4] = { w0.x, w0.y, w1.x, w1.y };

        #pragma unroll
        for (int i = 0; i < 8; i++)
            #pragma unroll
            for (int j = 0; j < 4; j++)
                ffma2(acc2[i][j], ad[i], bp[j]);
    }

    __syncthreads();   // all As reads done; reuse smem for partial tiles

    {
        float* buf = smem + grp * (BM * FDIM);
        #pragma unroll
        for (int i = 0; i < 8; i++) {
            const float2 f0 = unpk2(acc2[i][0]);
            const float2 f1 = unpk2(acc2[i][1]);
            const float2 f2 = unpk2(acc2[i][2]);
            const float2 f3 = unpk2(acc2[i][3]);
            float4 v0 = make_float4(f0.x, f0.y, f1.x, f1.y);
            float4 v1 = make_float4(f2.x, f2.y, f3.x, f3.y);
            *reinterpret_cast<float4*>(buf + (tr + i) * FDIM + tc + 0) = v0;
            *reinterpret_cast<float4*>(buf + (tr + i) * FDIM + tc + 4) = v1;
        }
    }

    __syncthreads();

    // final reduce + bias + store
    const int r  = tid >> 2;
    const int cb = (tid & 3) << 4;
    const int p  = blockIdx.x * BM + r;
    if (p < nOut) {
        #pragma unroll
        for (int j4 = 0; j4 < 16; j4 += 4) {
            float4 s0 = *reinterpret_cast<const float4*>(smem + 0 * (BM*FDIM) + r * FDIM + cb + j4);
            float4 s1 = *reinterpret_cast<const float4*>(smem + 1 * (BM*FDIM) + r * FDIM + cb + j4);
            float4 s2 = *reinterpret_cast<const float4*>(smem + 2 * (BM*FDIM) + r * FDIM + cb + j4);
            float4 s3 = *reinterpret_cast<const float4*>(smem + 3 * (BM*FDIM) + r * FDIM + cb + j4);
            float4 bb = *reinterpret_cast<const float4*>(bias + cb + j4);
            float4 v;
            v.x = s0.x + s1.x + s2.x + s3.x + bb.x;
            v.y = s0.y + s1.y + s2.y + s3.y + bb.y;
            v.z = s0.z + s1.z + s2.z + s3.z + bb.z;
            v.w = s0.w + s1.w + s2.w + s3.w + bb.w;
            *reinterpret_cast<float4*>(out + (long)p * FDIM + cb + j4) = v;
        }
    }
}

extern "C" void kernel_launch(void* const* d_in, const int* in_sizes, int n_in,
                              void* d_out, int out_size)
{
    const float* feat    = (const float*)d_in[0];
    const float* ipos    = (const float*)d_in[1];
    const float* opos    = (const float*)d_in[2];
    const float* extents = (const float*)d_in[3];
    const float* kern    = (const float*)d_in[4];
    const float* bias    = (const float*)d_in[5];
    const int*   nidx    = (const int*)d_in[6];

    float* out = (float*)d_out;

    const int nOut = in_sizes[2] / 3;
    const int deg  = in_sizes[6] / nOut;

    const int smemBytes = KDIM * AS_STRIDE * (int)sizeof(float); // 69632
    cudaFuncSetAttribute(spconv_fused_kernel,
                         cudaFuncAttributeMaxDynamicSharedMemorySize, smemBytes);

    const int grid = (nOut + BM - 1) / BM;
    spconv_fused_kernel<<<grid, 256, smemBytes>>>(feat, ipos, opos, extents,
                                                  kern, bias, nidx, out, nOut, deg);
}

// round 4
// speedup vs baseline: 1.2836x; 1.0972x over previous
#include <cuda_runtime.h>

// SPHeroConv fused, R4: L1-wavefront-minimized restructure.
//  Phase A: edge-parallel sph precompute -> smem (kills 4x redundant ipos/MUFU).
//  Phase B: 16 threads per feature row (4 chunks of 16 points) -> feat gather
//           at the 2048-wavefront minimum; As stored point-major, coalesced STS.128.
//  Stage 2: GEMM 8x8 micro-tile, 4-way k-split, A read as float4 along k with
//           XOR swizzle (conflict-free), B from global (L1-resident), FFMA2.

#define BM         64
#define CDIM       64
#define FDIM       64
#define KDIM       256
#define DEG_MAX    16
#define EPC_MAX    (BM * DEG_MAX)     // 1024
#define AS2_STRIDE 260                 // 256 + 4 pad (floats)

typedef unsigned long long u64;

__device__ __forceinline__ u64 dup2f(float x) {
    u64 r; asm("mov.b64 %0, {%1, %1};" : "=l"(r) : "f"(x)); return r;
}
__device__ __forceinline__ void ffma2(u64& d, u64 a, u64 b) {
    asm("fma.rn.f32x2 %0, %1, %2, %0;" : "+l"(d) : "l"(a), "l"(b));
}
__device__ __forceinline__ float2 unpk2(u64 v) {
    float lo, hi; asm("mov.b64 {%0, %1}, %2;" : "=f"(lo), "=f"(hi) : "l"(v));
    return make_float2(lo, hi);
}

__global__ __launch_bounds__(256, 2)
void spconv_fused_kernel(const float* __restrict__ feat,      // [N_IN, 64]
                         const float* __restrict__ ipos,      // [N_IN, 3]
                         const float* __restrict__ opos,      // [N_OUT, 3]
                         const float* __restrict__ extents,   // [1]
                         const float* __restrict__ kern,      // [256, 64]
                         const float* __restrict__ bias,      // [64]
                         const int*   __restrict__ nidx,      // [E]
                         float*       __restrict__ out,       // [N_OUT, 64]
                         int nOut, int deg)
{
    extern __shared__ float smem[];
    float*  As2  = smem;                                   // [BM][AS2_STRIDE]
    float4* sphs = (float4*)(smem + BM * AS2_STRIDE);      // [EPC_MAX]
    int*    ns   = (int*)(smem + BM * AS2_STRIDE + 4 * EPC_MAX);

    const int tid = threadIdx.x;

    // ---------------- phase A: edge-parallel sph precompute ------------------
    {
        const long E_total = (long)nOut * deg;
        const int  epc     = BM * deg;
        const long cta_eb  = (long)blockIdx.x * epc;
        const float inv_ext = __fdividef(1.0f, extents[0]);

        #pragma unroll
        for (int i = 0; i < 4; i++) {
            const int el = tid + i * 256;
            if (el < epc) {
                const long ge = cta_eb + el;
                float4 sph = make_float4(0.f, 0.f, 0.f, 0.f);
                int n = 0;
                if (ge < E_total) {
                    n = nidx[ge];
                    const int pt = blockIdx.x * BM + el / deg;
                    const float ox = opos[pt * 3 + 0];
                    const float oy = opos[pt * 3 + 1];
                    const float oz = opos[pt * 3 + 2];
                    const float dx = ipos[n * 3 + 0] - ox;
                    const float dy = ipos[n * 3 + 1] - oy;
                    const float dz = ipos[n * 3 + 2] - oz;
                    const float r2p = dx * dx + dy * dy;
                    const float r2  = r2p + dz * dz;
                    const float rinv  = rsqrtf(fmaxf(r2,  1e-20f));
                    const float rpinv = rsqrtf(fmaxf(r2p, 1e-20f));
                    sph.x = (r2 * rinv) * inv_ext;
                    sph.y = dz * rinv;
                    sph.z = dy * rpinv;
                    sph.w = dx * rpinv;
                }
                sphs[el] = sph;
                ns[el]   = n;
            }
        }
    }
    __syncthreads();

    // ---------------- phase B: gather + accumulate, 16 thr/row ---------------
    // thread (prow, cq): point chunk*16+prow, channels [4cq, 4cq+4)
    const int cq   = tid & 15;
    const int prow = tid >> 4;

    #pragma unroll
    for (int chunk = 0; chunk < 4; chunk++) {
        const int ptl = chunk * 16 + prow;

        u64 g2[4][2];
        #pragma unroll
        for (int s = 0; s < 4; s++) { g2[s][0] = 0ull; g2[s][1] = 0ull; }

        const int eb = ptl * deg;
        #pragma unroll 4
        for (int k = 0; k < deg; k++) {
            const int el = eb + k;
            const int n  = ns[el];
            const float4 sph = sphs[el];
            const ulonglong2 w =
                *reinterpret_cast<const ulonglong2*>(feat + (long)n * CDIM + cq * 4);
            const u64 s0 = dup2f(sph.x), s1 = dup2f(sph.y),
                      s2 = dup2f(sph.z), s3 = dup2f(sph.w);
            ffma2(g2[0][0], s0, w.x); ffma2(g2[0][1], s0, w.y);
            ffma2(g2[1][0], s1, w.x); ffma2(g2[1][1], s1, w.y);
            ffma2(g2[2][0], s2, w.x); ffma2(g2[2][1], s2, w.y);
            ffma2(g2[3][0], s3, w.x); ffma2(g2[3][1], s3, w.y);
        }

        // coalesced STS.128: As2[ptl][ (s*64 + 4cq) ^ swz(ptl) ]
        const int swz = ((ptl >> 3) & 3) << 2;
        float* dst = As2 + ptl * AS2_STRIDE;
        #pragma unroll
        for (int s = 0; s < 4; s++) {
            const float2 f0 = unpk2(g2[s][0]);
            const float2 f1 = unpk2(g2[s][1]);
            float4 v = make_float4(f0.x, f0.y, f1.x, f1.y);
            *reinterpret_cast<float4*>(dst + ((s * CDIM + cq * 4) ^ swz)) = v;
        }
    }

    __syncthreads();

    // ---------------- stage 2: GEMM, 8x8 tile, 4-way k-split -----------------
    const int grp = tid >> 6;            // k-split group 0..3
    const int gt  = tid & 63;
    const int tr  = (gt >> 3) << 3;      // row base (point)
    const int tc  = (gt & 7) << 3;       // col base (feature)
    const int k0  = grp << 6;

    u64 acc2[8][4];
    #pragma unroll
    for (int i = 0; i < 8; i++)
        #pragma unroll
        for (int j = 0; j < 4; j++) acc2[i][j] = 0ull;

    for (int k4 = 0; k4 < 16; k4++) {
        const int kbase = k0 + k4 * 4;

        float4 a[8];
        #pragma unroll
        for (int i = 0; i < 8; i++) {
            const int r = tr + i;
            a[i] = *reinterpret_cast<const float4*>(
                As2 + r * AS2_STRIDE + (kbase ^ (((r >> 3) & 3) << 2)));
        }

        #define STEP(DK, MEM)                                                        \
        {                                                                            \
            const ulonglong2* kb =                                                   \
                reinterpret_cast<const ulonglong2*>(kern + (kbase + DK) * FDIM + tc);\
            const ulonglong2 w0 = kb[0];                                             \
            const ulonglong2 w1 = kb[1];                                             \
            _Pragma("unroll")                                                        \
            for (int i = 0; i < 8; i++) {                                            \
                const u64 ad = dup2f(a[i].MEM);                                      \
                ffma2(acc2[i][0], ad, w0.x); ffma2(acc2[i][1], ad, w0.y);            \
                ffma2(acc2[i][2], ad, w1.x); ffma2(acc2[i][3], ad, w1.y);            \
            }                                                                        \
        }
        STEP(0, x) STEP(1, y) STEP(2, z) STEP(3, w)
        #undef STEP
    }

    __syncthreads();   // all As2 reads done; reuse smem for partial tiles

    {
        float* buf = smem + grp * (BM * FDIM);
        #pragma unroll
        for (int i = 0; i < 8; i++) {
            const float2 f0 = unpk2(acc2[i][0]);
            const float2 f1 = unpk2(acc2[i][1]);
            const float2 f2 = unpk2(acc2[i][2]);
            const float2 f3 = unpk2(acc2[i][3]);
            *reinterpret_cast<float4*>(buf + (tr + i) * FDIM + tc + 0) =
                make_float4(f0.x, f0.y, f1.x, f1.y);
            *reinterpret_cast<float4*>(buf + (tr + i) * FDIM + tc + 4) =
                make_float4(f2.x, f2.y, f3.x, f3.y);
        }
    }

    __syncthreads();

    // final reduce + bias + store
    const int r  = tid >> 2;
    const int cb = (tid & 3) << 4;
    const int p  = blockIdx.x * BM + r;
    if (p < nOut) {
        #pragma unroll
        for (int j4 = 0; j4 < 16; j4 += 4) {
            float4 s0 = *reinterpret_cast<const float4*>(smem + 0 * (BM*FDIM) + r * FDIM + cb + j4);
            float4 s1 = *reinterpret_cast<const float4*>(smem + 1 * (BM*FDIM) + r * FDIM + cb + j4);
            float4 s2 = *reinterpret_cast<const float4*>(smem + 2 * (BM*FDIM) + r * FDIM + cb + j4);
            float4 s3 = *reinterpret_cast<const float4*>(smem + 3 * (BM*FDIM) + r * FDIM + cb + j4);
            float4 bb = *reinterpret_cast<const float4*>(bias + cb + j4);
            float4 v;
            v.x = s0.x + s1.x + s2.x + s3.x + bb.x;
            v.y = s0.y + s1.y + s2.y + s3.y + bb.y;
            v.z = s0.z + s1.z + s2.z + s3.z + bb.z;
            v.w = s0.w + s1.w + s2.w + s3.w + bb.w;
            *reinterpret_cast<float4*>(out + (long)p * FDIM + cb + j4) = v;
        }
    }
}

extern "C" void kernel_launch(void* const* d_in, const int* in_sizes, int n_in,
                              void* d_out, int out_size)
{
    const float* feat    = (const float*)d_in[0];
    const float* ipos    = (const float*)d_in[1];
    const float* opos    = (const float*)d_in[2];
    const float* extents = (const float*)d_in[3];
    const float* kern    = (const float*)d_in[4];
    const float* bias    = (const float*)d_in[5];
    const int*   nidx    = (const int*)d_in[6];

    float* out = (float*)d_out;

    const int nOut = in_sizes[2] / 3;
    const int deg  = in_sizes[6] / nOut;

    // smem: As2 (64*260) + sphs (1024 float4) + ns (1024 int)
    const int smemBytes = (BM * AS2_STRIDE + 4 * EPC_MAX + EPC_MAX) * (int)sizeof(float); // 87040
    cudaFuncSetAttribute(spconv_fused_kernel,
                         cudaFuncAttributeMaxDynamicSharedMemorySize, smemBytes);

    const int grid = (nOut + BM - 1) / BM;
    spconv_fused_kernel<<<grid, 256, smemBytes>>>(feat, ipos, opos, extents,
                                                  kern, bias, nidx, out, nOut, deg);
}